// round 14
// baseline (speedup 1.0000x reference)
#include <cuda_runtime.h>
#include <cuda_bf16.h>
#include <cuda_fp16.h>

// BoundaryLoss: loss = sum_{b,c,d,h,w} Gx(q)^2 + 2*Gy(q)^2 (normalized),
// q = softmax(pred, axis=C) - onehot(target); 2-D sobel per depth slice.
// pred (2,4,96,160,160) f32, target (2,96,160,160) i32.
// R14: warp-specialized producer/consumer. 592 blocks x 3-4 contiguous
// tiles (one wave). 5 producer warps do LDG+softmax -> fp16 q into a
// double buffer; 5 consumer warps do the half2 sobel. Named-barrier
// handoff; phases overlap instead of alternating.

#define BB 2
#define CC 4
#define DD 96
#define HH 160
#define WW 160

#define TH 16                       // output rows per tile
#define HALO (TH + 2)               // 18
#define RTILES (HH / TH)            // 10
#define NTILE (BB * DD * RTILES)    // 1920
#define NPBLK 592                   // 148 SMs x 4 blocks, one wave
#define K4BLK 144                   // first 144 blocks take 4 tiles (rest 3)
#define NTHREADS 320
#define NPROD 160                   // producer threads (5 warps)
#define NWARP (NTHREADS / 32)
#define PITCHB 336                  // bytes/row: [4 guard][160 data][4 guard] halfs
#define BUFB (CC * HALO * PITCHB)   // 24192 bytes per buffer

#define CHSTR4 (DD * HH * WW / 4)

__device__ float g_partial[NPBLK];
__device__ int   g_count = 0;

__device__ __forceinline__ __half2 u2h(unsigned x) {
    return *reinterpret_cast<__half2*>(&x);
}
__device__ __forceinline__ unsigned h2u(__half2 x) {
    return *reinterpret_cast<unsigned*>(&x);
}

#define BAR_SYNC(ID)   asm volatile("bar.sync %0, %1;"   :: "r"(ID), "r"(NTHREADS) : "memory")
#define BAR_ARRIVE(ID) asm volatile("bar.arrive %0, %1;" :: "r"(ID), "r"(NTHREADS) : "memory")
// barrier ids: full buffer 0/1 -> 1/2 ; free buffer 0/1 -> 3/4

__device__ __forceinline__ void softmax_store(
    unsigned char* qb, const float4 x0, const float4 x1,
    const float4 x2, const float4 x3, const int4 tt, int j, int vc)
{
    float4 q0, q1, q2, q3;
    {
        float e0 = __expf(x0.x), e1 = __expf(x1.x), e2 = __expf(x2.x), e3 = __expf(x3.x);
        float r = __frcp_rn(e0 + e1 + e2 + e3);
        q0.x = e0 * r - (tt.x == 0); q1.x = e1 * r - (tt.x == 1);
        q2.x = e2 * r - (tt.x == 2); q3.x = e3 * r - (tt.x == 3);
    }
    {
        float e0 = __expf(x0.y), e1 = __expf(x1.y), e2 = __expf(x2.y), e3 = __expf(x3.y);
        float r = __frcp_rn(e0 + e1 + e2 + e3);
        q0.y = e0 * r - (tt.y == 0); q1.y = e1 * r - (tt.y == 1);
        q2.y = e2 * r - (tt.y == 2); q3.y = e3 * r - (tt.y == 3);
    }
    {
        float e0 = __expf(x0.z), e1 = __expf(x1.z), e2 = __expf(x2.z), e3 = __expf(x3.z);
        float r = __frcp_rn(e0 + e1 + e2 + e3);
        q0.z = e0 * r - (tt.z == 0); q1.z = e1 * r - (tt.z == 1);
        q2.z = e2 * r - (tt.z == 2); q3.z = e3 * r - (tt.z == 3);
    }
    {
        float e0 = __expf(x0.w), e1 = __expf(x1.w), e2 = __expf(x2.w), e3 = __expf(x3.w);
        float r = __frcp_rn(e0 + e1 + e2 + e3);
        q0.w = e0 * r - (tt.w == 0); q1.w = e1 * r - (tt.w == 1);
        q2.w = e2 * r - (tt.w == 2); q3.w = e3 * r - (tt.w == 3);
    }
    const int bo = 8 + 8 * vc + j * PITCHB;
    *(uint2*)(qb + 0 * HALO * PITCHB + bo) =
        make_uint2(h2u(__floats2half2_rn(q0.x, q0.y)), h2u(__floats2half2_rn(q0.z, q0.w)));
    *(uint2*)(qb + 1 * HALO * PITCHB + bo) =
        make_uint2(h2u(__floats2half2_rn(q1.x, q1.y)), h2u(__floats2half2_rn(q1.z, q1.w)));
    *(uint2*)(qb + 2 * HALO * PITCHB + bo) =
        make_uint2(h2u(__floats2half2_rn(q2.x, q2.y)), h2u(__floats2half2_rn(q2.z, q2.w)));
    *(uint2*)(qb + 3 * HALO * PITCHB + bo) =
        make_uint2(h2u(__floats2half2_rn(q3.x, q3.y)), h2u(__floats2half2_rn(q3.z, q3.w)));
}

__device__ __forceinline__ void zero_store(unsigned char* qb, int j, int vc)
{
    const int bo = 8 + 8 * vc + j * PITCHB;
    const uint2 z = make_uint2(0u, 0u);
    *(uint2*)(qb + 0 * HALO * PITCHB + bo) = z;
    *(uint2*)(qb + 1 * HALO * PITCHB + bo) = z;
    *(uint2*)(qb + 2 * HALO * PITCHB + bo) = z;
    *(uint2*)(qb + 3 * HALO * PITCHB + bo) = z;
}

__global__ __launch_bounds__(NTHREADS, 4)
void bl_main_kernel(const float* __restrict__ pred,
                    const int*   __restrict__ target,
                    float*       __restrict__ out)
{
    __shared__ __align__(16) unsigned char qsm[2 * BUFB];   // 48384 B
    __shared__ float warpsum[NWARP];
    __shared__ double dwarpsum[NWARP];
    __shared__ bool  is_last;

    const int tid = threadIdx.x;

    // ---- tile range for this block (contiguous, R12 layout) ----
    int t0, ntl;
    if (blockIdx.x < K4BLK) { t0 = blockIdx.x * 4;                       ntl = 4; }
    else                    { t0 = K4BLK * 4 + (blockIdx.x - K4BLK) * 3; ntl = 3; }

    // ---- guard halfs in BOTH buffers: zero [0..3] and [164..167] ----
    for (int p = tid; p < 2 * CC * HALO * 2; p += NTHREADS) {
        const int bufc = p / (CC * HALO * 2);
        const int rem  = p - bufc * (CC * HALO * 2);
        const int c    = rem / (HALO * 2);
        const int r2   = rem - c * (HALO * 2);
        const int row  = r2 >> 1;
        const int side = r2 & 1;
        *(uint2*)(qsm + bufc * BUFB + (c * HALO + row) * PITCHB + (side ? 328 : 0))
            = make_uint2(0u, 0u);
    }
    __syncthreads();

    float axs = 0.f, ays = 0.f;

    if (tid < NPROD) {
        // ================= PRODUCER (warps 0-4) =================
        int it = 0;
        for (int t = t0; t < t0 + ntl; t++, it++) {
            const int buf   = it & 1;
            const int rt    = t % RTILES;
            const int slice = t / RTILES;
            const int b     = slice / DD;
            const int d     = slice - b * DD;
            const int h0    = rt * TH;
            const float* pred_bd = pred + (size_t)(b * CC * DD + d) * (HH * WW);
            const int*   tgt_bd  = target + (size_t)slice * (HH * WW);
            unsigned char* qb = qsm + buf * BUFB;

            if (it >= 2) BAR_SYNC(3 + buf);          // wait buffer free

            for (int p = tid; p < HALO * (WW / 4); p += NPROD) {
                const int j  = p / (WW / 4);
                const int vc = p - j * (WW / 4);
                const int h  = h0 + j - 1;
                if ((unsigned)h < (unsigned)HH) {
                    const float4* pr = (const float4*)(pred_bd + h * WW) + vc;
                    softmax_store(qb, pr[0], pr[CHSTR4], pr[2 * CHSTR4], pr[3 * CHSTR4],
                                  ((const int4*)(tgt_bd + h * WW))[vc], j, vc);
                } else {
                    zero_store(qb, j, vc);
                }
            }
            BAR_ARRIVE(1 + buf);                     // publish full
        }
    } else {
        // ================= CONSUMER (warps 5-9) =================
        const int ct   = tid - NPROD;                // 0..159
        const int c2   = ct / 40;                    // class
        const int g2   = ct - c2 * 40;               // 4-col group
        const int off2 = 8 * g2;
        const __half2 TWOH = __half2half2(__float2half(2.0f));
        const __half2 ZERO = __half2half2(__float2half(0.0f));

        int it = 0;
        for (int t = t0; t < t0 + ntl; t++, it++) {
            const int buf = it & 1;
            BAR_SYNC(1 + buf);                       // wait buffer full

            const unsigned char* rp = qsm + buf * BUFB + c2 * HALO * PITCHB;
            __half2 pu[2], pv[2], cu[2], cv[2];

#define ROW_UV(U, V)                                                      \
    {                                                                     \
        const unsigned eL = *(const unsigned*)(rp + 4 + off2);            \
        const uint2    M  = *(const uint2*)(rp + 8 + off2);               \
        const unsigned eR = *(const unsigned*)(rp + 16 + off2);           \
        const __half2 S0 = u2h(__byte_perm(eL, M.x, 0x5432));             \
        const __half2 S1 = u2h(__byte_perm(M.x, M.y, 0x5432));            \
        const __half2 S2 = u2h(__byte_perm(M.y, eR, 0x5432));             \
        U[0] = __hfma2(u2h(M.x), TWOH, __hadd2(S0, S1));                  \
        U[1] = __hfma2(u2h(M.y), TWOH, __hadd2(S1, S2));                  \
        V[0] = __hsub2(S1, S0);                                           \
        V[1] = __hsub2(S2, S1);                                           \
        rp += PITCHB;                                                     \
    }

            ROW_UV(pu, pv);
            ROW_UV(cu, cv);

#pragma unroll
            for (int qb4 = 0; qb4 < 4; qb4++) {      // 4 groups of 4 rows
                __half2 axh = ZERO, ayh = ZERO;
#pragma unroll
                for (int k = 0; k < 4; k++) {
                    __half2 nu[2], nv[2];
                    ROW_UV(nu, nv);
#pragma unroll
                    for (int i = 0; i < 2; i++) {
                        const __half2 gx = __hfma2(cv[i], TWOH, __hadd2(pv[i], nv[i]));
                        const __half2 gy = __hsub2(nu[i], pu[i]);
                        axh = __hfma2(gx, gx, axh);
                        ayh = __hfma2(gy, gy, ayh);
                        pu[i] = cu[i]; pv[i] = cv[i];
                        cu[i] = nu[i]; cv[i] = nv[i];
                    }
                }
                const float2 fx = __half22float2(axh);
                const float2 fy = __half22float2(ayh);
                axs += fx.x + fx.y;
                ays += fy.x + fy.y;
            }
#undef ROW_UV
            BAR_ARRIVE(3 + buf);                     // release buffer
        }
    }

    float acc = axs + 2.f * ays;                     // producers: 0

    // ---- block reduction -> per-block partial ----
    __syncthreads();
#pragma unroll
    for (int o = 16; o > 0; o >>= 1)
        acc += __shfl_down_sync(0xffffffffu, acc, o);
    if ((tid & 31) == 0) warpsum[tid >> 5] = acc;
    __syncthreads();

    if (tid == 0) {
        float sm = 0.f;
#pragma unroll
        for (int i = 0; i < NWARP; i++) sm += warpsum[i];
        g_partial[blockIdx.x] = sm;
        __threadfence();
        is_last = (atomicAdd(&g_count, 1) == NPBLK - 1);
    }
    __syncthreads();

    // ---- last block: final reduction + output + counter reset ----
    if (is_last) {
        double sd = 0.0;
        for (int i = tid; i < NPBLK; i += NTHREADS) sd += (double)g_partial[i];
#pragma unroll
        for (int o = 16; o > 0; o >>= 1)
            sd += __shfl_down_sync(0xffffffffu, sd, o);
        if ((tid & 31) == 0) dwarpsum[tid >> 5] = sd;
        __syncthreads();
        if (tid == 0) {
            double tot = 0.0;
#pragma unroll
            for (int i = 0; i < NWARP; i++) tot += dwarpsum[i];
            const double per_tensor = (double)BB * (DD + 2) * (HH + 2) * (WW + 2);
            out[0] = (float)(tot / per_tensor / (double)CC);
            g_count = 0;
        }
    }
}

extern "C" void kernel_launch(void* const* d_in, const int* in_sizes, int n_in,
                              void* d_out, int out_size)
{
    const float* pred   = (const float*)d_in[0];
    const int*   target = (const int*)d_in[1];
    float*       out    = (float*)d_out;

    bl_main_kernel<<<NPBLK, NTHREADS>>>(pred, target, out);
}

// round 15
// speedup vs baseline: 1.1633x; 1.1633x over previous
#include <cuda_runtime.h>
#include <cuda_bf16.h>
#include <cuda_fp16.h>

// BoundaryLoss: loss = sum_{b,c,d,h,w} Gx(q)^2 + 2*Gy(q)^2 (normalized),
// q = softmax(pred, axis=C) - onehot(target); 2-D sobel per depth slice.
// pred (2,4,96,160,160) f32, target (2,96,160,160) i32.
// R15 = R13 (one wave, ring buffer, fp16 q smem, half2 sobel) with a
// MUFU-minimal softmax: normalize by channel 3 (e3==1 -> 3 ex2 + 1
// rcp.approx per voxel instead of 4 exp + rcp.rn+Newton).

#define BB 2
#define CC 4
#define DD 96
#define HH 160
#define WW 160

#define TH 16                       // output rows per tile
#define HALO (TH + 2)               // 18 (ring size)
#define RTILES (HH / TH)            // 10
#define NTILE (BB * DD * RTILES)    // 1920
#define NPBLK 592                   // 148 SMs x 4 blocks, one wave
#define K4BLK 144                   // first 144 blocks take 4 tiles (rest 3)
#define NTHREADS 320
#define NWARP (NTHREADS / 32)
#define PITCHB 336                  // bytes/row: [4 guard][160 data][4 guard] halfs

#define CHSTR4 (DD * HH * WW / 4)

__device__ float g_partial[NPBLK];
__device__ int   g_count = 0;

__device__ __forceinline__ __half2 u2h(unsigned x) {
    return *reinterpret_cast<__half2*>(&x);
}
__device__ __forceinline__ unsigned h2u(__half2 x) {
    return *reinterpret_cast<unsigned*>(&x);
}
__device__ __forceinline__ float ex2a(float x) {
    float r; asm("ex2.approx.f32 %0, %1;" : "=f"(r) : "f"(x)); return r;
}
__device__ __forceinline__ float rcpa(float x) {
    float r; asm("rcp.approx.f32 %0, %1;" : "=f"(r) : "f"(x)); return r;
}

#define LOG2E 1.4426950408889634f

// softmax(4) - onehot -> packed fp16 uint2, store to 4 class rows at slot.
// Channel-3-normalized: e_i = 2^(K*(x_i - x3)), e3 = 1.
__device__ __forceinline__ void softmax_store(
    unsigned char* qsm, const float4 x0, const float4 x1,
    const float4 x2, const float4 x3, const int4 tt, int slot, int vc)
{
    float4 q0, q1, q2, q3;
    {
        const float nb = -LOG2E * x3.x;
        const float e0 = ex2a(__fmaf_rn(x0.x, LOG2E, nb));
        const float e1 = ex2a(__fmaf_rn(x1.x, LOG2E, nb));
        const float e2 = ex2a(__fmaf_rn(x2.x, LOG2E, nb));
        const float r  = rcpa(e0 + e1 + e2 + 1.0f);
        q0.x = e0 * r - (tt.x == 0); q1.x = e1 * r - (tt.x == 1);
        q2.x = e2 * r - (tt.x == 2); q3.x = r - (tt.x == 3);
    }
    {
        const float nb = -LOG2E * x3.y;
        const float e0 = ex2a(__fmaf_rn(x0.y, LOG2E, nb));
        const float e1 = ex2a(__fmaf_rn(x1.y, LOG2E, nb));
        const float e2 = ex2a(__fmaf_rn(x2.y, LOG2E, nb));
        const float r  = rcpa(e0 + e1 + e2 + 1.0f);
        q0.y = e0 * r - (tt.y == 0); q1.y = e1 * r - (tt.y == 1);
        q2.y = e2 * r - (tt.y == 2); q3.y = r - (tt.y == 3);
    }
    {
        const float nb = -LOG2E * x3.z;
        const float e0 = ex2a(__fmaf_rn(x0.z, LOG2E, nb));
        const float e1 = ex2a(__fmaf_rn(x1.z, LOG2E, nb));
        const float e2 = ex2a(__fmaf_rn(x2.z, LOG2E, nb));
        const float r  = rcpa(e0 + e1 + e2 + 1.0f);
        q0.z = e0 * r - (tt.z == 0); q1.z = e1 * r - (tt.z == 1);
        q2.z = e2 * r - (tt.z == 2); q3.z = r - (tt.z == 3);
    }
    {
        const float nb = -LOG2E * x3.w;
        const float e0 = ex2a(__fmaf_rn(x0.w, LOG2E, nb));
        const float e1 = ex2a(__fmaf_rn(x1.w, LOG2E, nb));
        const float e2 = ex2a(__fmaf_rn(x2.w, LOG2E, nb));
        const float r  = rcpa(e0 + e1 + e2 + 1.0f);
        q0.w = e0 * r - (tt.w == 0); q1.w = e1 * r - (tt.w == 1);
        q2.w = e2 * r - (tt.w == 2); q3.w = r - (tt.w == 3);
    }
    const int bo = 8 + 8 * vc + slot * PITCHB;
    *(uint2*)(qsm + 0 * HALO * PITCHB + bo) =
        make_uint2(h2u(__floats2half2_rn(q0.x, q0.y)), h2u(__floats2half2_rn(q0.z, q0.w)));
    *(uint2*)(qsm + 1 * HALO * PITCHB + bo) =
        make_uint2(h2u(__floats2half2_rn(q1.x, q1.y)), h2u(__floats2half2_rn(q1.z, q1.w)));
    *(uint2*)(qsm + 2 * HALO * PITCHB + bo) =
        make_uint2(h2u(__floats2half2_rn(q2.x, q2.y)), h2u(__floats2half2_rn(q2.z, q2.w)));
    *(uint2*)(qsm + 3 * HALO * PITCHB + bo) =
        make_uint2(h2u(__floats2half2_rn(q3.x, q3.y)), h2u(__floats2half2_rn(q3.z, q3.w)));
}

__device__ __forceinline__ void zero_store(unsigned char* qsm, int slot, int vc)
{
    const int bo = 8 + 8 * vc + slot * PITCHB;
    const uint2 z = make_uint2(0u, 0u);
    *(uint2*)(qsm + 0 * HALO * PITCHB + bo) = z;
    *(uint2*)(qsm + 1 * HALO * PITCHB + bo) = z;
    *(uint2*)(qsm + 2 * HALO * PITCHB + bo) = z;
    *(uint2*)(qsm + 3 * HALO * PITCHB + bo) = z;
}

__global__ __launch_bounds__(NTHREADS, 4)
void bl_main_kernel(const float* __restrict__ pred,
                    const int*   __restrict__ target,
                    float*       __restrict__ out)
{
    __shared__ __align__(16) unsigned char qsm[CC * HALO * PITCHB];  // 24192 B
    __shared__ float warpsum[NWARP];
    __shared__ double dwarpsum[NWARP];
    __shared__ bool  is_last;

    const int tid = threadIdx.x;

    // ---- tile range for this block (contiguous, one-wave layout) ----
    int t0, ntl;
    if (blockIdx.x < K4BLK) { t0 = blockIdx.x * 4;                       ntl = 4; }
    else                    { t0 = K4BLK * 4 + (blockIdx.x - K4BLK) * 3; ntl = 3; }

    // ---- guard halfs: zero [0..3] and [164..167] per (c,slot); once ----
    if (tid < CC * HALO * 2) {
        const int c    = tid / (HALO * 2);
        const int rem  = tid - c * (HALO * 2);
        const int row  = rem >> 1;
        const int side = rem & 1;
        *(uint2*)(qsm + (c * HALO + row) * PITCHB + (side ? 328 : 0)) = make_uint2(0u, 0u);
    }

    // phase-1 incremental mapping (fixed): jn = tid/40 (0..7), vc = tid%40
    const int jn1  = tid / 40;
    const int vcn  = tid - jn1 * 40;

    // phase-2 mapping: (class c2, 4-col group g2, 8-row strip s2); 4*40*2=320
    const int c2   = tid / 80;
    const int rem2 = tid - c2 * 80;
    const int s2   = rem2 / 40;
    const int g2   = rem2 - s2 * 40;
    const int off2 = 8 * g2;
    unsigned char* const base_c2 = qsm + c2 * HALO * PITCHB;

    float axs = 0.f, ays = 0.f;

    int cur_slice = -1;
    int rslot0 = 0;                 // ring slot of current tile's halo row 0

    for (int t = t0; t < t0 + ntl; t++) {
        const int rt    = t % RTILES;
        const int slice = t / RTILES;
        const int b     = slice / DD;
        const int d     = slice - b * DD;
        const int h0    = rt * TH;

        const float* pred_bd = pred + (size_t)(b * CC * DD + d) * (HH * WW);
        const int*   tgt_bd  = target + (size_t)slice * (HH * WW);

        if (slice != cur_slice) {
            // ---- full 18-row load into slots 0..17 ----
            cur_slice = slice;
            rslot0 = 0;
            for (int p = tid; p < HALO * (WW / 4); p += NTHREADS) {
                const int j  = p / (WW / 4);
                const int vc = p - j * (WW / 4);
                const int h  = h0 + j - 1;
                if ((unsigned)h < (unsigned)HH) {
                    const float4* pr = (const float4*)(pred_bd + h * WW) + vc;
                    softmax_store(qsm, pr[0], pr[CHSTR4], pr[2 * CHSTR4], pr[3 * CHSTR4],
                                  ((const int4*)(tgt_bd + h * WW))[vc], j, vc);
                } else {
                    zero_store(qsm, j, vc);
                }
            }
        } else {
            // ---- incremental: 16 new rows (this tile's halo rows 2..17) ----
            const int p = rslot0;                    // previous tile's slot0
            {
                const int h = h0 + 1 + jn1;          // <= h0+8 <= 152: valid
                int sl = p + jn1; if (sl >= HALO) sl -= HALO;
                const float4* pr = (const float4*)(pred_bd + h * WW) + vcn;
                softmax_store(qsm, pr[0], pr[CHSTR4], pr[2 * CHSTR4], pr[3 * CHSTR4],
                              ((const int4*)(tgt_bd + h * WW))[vcn], sl, vcn);
            }
            {
                const int jn2 = jn1 + 8;             // 8..15
                const int h = h0 + 1 + jn2;          // may be HH at rt==9
                int sl = p + jn2; if (sl >= HALO) sl -= HALO;
                if (h < HH) {
                    const float4* pr = (const float4*)(pred_bd + h * WW) + vcn;
                    softmax_store(qsm, pr[0], pr[CHSTR4], pr[2 * CHSTR4], pr[3 * CHSTR4],
                                  ((const int4*)(tgt_bd + h * WW))[vcn], sl, vcn);
                } else {
                    zero_store(qsm, sl, vcn);
                }
            }
            rslot0 = p + 16; if (rslot0 >= HALO) rslot0 -= HALO;
        }
        __syncthreads();

        // ---- Phase 2: separable sobel in packed half2, ring-slot walk ----
        {
            const __half2 TWOH = __half2half2(__float2half(2.0f));
            const __half2 ZERO = __half2half2(__float2half(0.0f));
            int sl = rslot0 + s2 * 8; if (sl >= HALO) sl -= HALO;

            __half2 pu[2], pv[2], cu[2], cv[2];

#define ROW_UV(U, V)                                                      \
    {                                                                     \
        const unsigned char* rp = base_c2 + sl * PITCHB;                  \
        const unsigned eL = *(const unsigned*)(rp + 4 + off2);            \
        const uint2    M  = *(const uint2*)(rp + 8 + off2);               \
        const unsigned eR = *(const unsigned*)(rp + 16 + off2);           \
        const __half2 S0 = u2h(__byte_perm(eL, M.x, 0x5432));             \
        const __half2 S1 = u2h(__byte_perm(M.x, M.y, 0x5432));            \
        const __half2 S2 = u2h(__byte_perm(M.y, eR, 0x5432));             \
        U[0] = __hfma2(u2h(M.x), TWOH, __hadd2(S0, S1));                  \
        U[1] = __hfma2(u2h(M.y), TWOH, __hadd2(S1, S2));                  \
        V[0] = __hsub2(S1, S0);                                           \
        V[1] = __hsub2(S2, S1);                                           \
        if (++sl == HALO) sl = 0;                                         \
    }

            ROW_UV(pu, pv);
            ROW_UV(cu, cv);

#pragma unroll
            for (int half_blk = 0; half_blk < 2; half_blk++) {
                __half2 axh = ZERO, ayh = ZERO;
#pragma unroll
                for (int k = 0; k < 4; k++) {
                    __half2 nu[2], nv[2];
                    ROW_UV(nu, nv);
#pragma unroll
                    for (int i = 0; i < 2; i++) {
                        const __half2 gx = __hfma2(cv[i], TWOH, __hadd2(pv[i], nv[i]));
                        const __half2 gy = __hsub2(nu[i], pu[i]);
                        axh = __hfma2(gx, gx, axh);
                        ayh = __hfma2(gy, gy, ayh);
                        pu[i] = cu[i]; pv[i] = cv[i];
                        cu[i] = nu[i]; cv[i] = nv[i];
                    }
                }
                const float2 fx = __half22float2(axh);
                const float2 fy = __half22float2(ayh);
                axs += fx.x + fx.y;
                ays += fy.x + fy.y;
            }
#undef ROW_UV
        }

        if (t + 1 < t0 + ntl) __syncthreads();   // ring overwrite hazard
    }

    float acc = axs + 2.f * ays;

    // ---- block reduction -> per-block partial ----
#pragma unroll
    for (int o = 16; o > 0; o >>= 1)
        acc += __shfl_down_sync(0xffffffffu, acc, o);
    if ((tid & 31) == 0) warpsum[tid >> 5] = acc;
    __syncthreads();

    if (tid == 0) {
        float sm = 0.f;
#pragma unroll
        for (int i = 0; i < NWARP; i++) sm += warpsum[i];
        g_partial[blockIdx.x] = sm;
        __threadfence();
        is_last = (atomicAdd(&g_count, 1) == NPBLK - 1);
    }
    __syncthreads();

    // ---- last block: final reduction + output + counter reset ----
    if (is_last) {
        double sd = 0.0;
        for (int i = tid; i < NPBLK; i += NTHREADS) sd += (double)g_partial[i];
#pragma unroll
        for (int o = 16; o > 0; o >>= 1)
            sd += __shfl_down_sync(0xffffffffu, sd, o);
        if ((tid & 31) == 0) dwarpsum[tid >> 5] = sd;
        __syncthreads();
        if (tid == 0) {
            double tot = 0.0;
#pragma unroll
            for (int i = 0; i < NWARP; i++) tot += dwarpsum[i];
            const double per_tensor = (double)BB * (DD + 2) * (HH + 2) * (WW + 2);
            out[0] = (float)(tot / per_tensor / (double)CC);
            g_count = 0;
        }
    }
}

extern "C" void kernel_launch(void* const* d_in, const int* in_sizes, int n_in,
                              void* d_out, int out_size)
{
    const float* pred   = (const float*)d_in[0];
    const int*   target = (const int*)d_in[1];
    float*       out    = (float*)d_out;

    bl_main_kernel<<<NPBLK, NTHREADS>>>(pred, target, out);
}